// round 7
// baseline (speedup 1.0000x reference)
#include <cuda_runtime.h>
#include <cuda_bf16.h>

// RNN: B=8192, T=2048, I=2, H=20
//   h_{t+1} = tanh(x_t @ W_ih^T + b_ih + b_hh + h_t @ W_hh^T)
//   out = h_T @ fc_w^T + fc_b ; h_state = h_T
//
// R7: 8 lanes per row = 4 parts (5 outputs each) x 2 k-halves (pair-
// interleaved). 65536 threads -> 2048 warps (3.46/SMSP): double the latency
// coverage of R3/R5, which were chain-bound at 1.73 warps/SMSP.
// Per step: 5x LDS.64 (h pairs of my k-half), 26 fma2 (chain depth 6),
// shfl_xor(4) combines the two k-half partials, tanh, STS by kh0.
// x-broadcast shfls hoisted to chunk top (8 steps/chunk), out of the chain.

#define BB 8192
#define TT 2048
#define HH 20
#define JPT 5          // outputs per thread
#define LPR 8          // lanes per row
#define RPW 4          // rows per warp
#define RPC 8          // rows per CTA (2 warps)

typedef unsigned long long u64;

__device__ __forceinline__ u64 pack2(float lo, float hi) {
    u64 r; asm("mov.b64 %0, {%1, %2};" : "=l"(r) : "f"(lo), "f"(hi)); return r;
}
__device__ __forceinline__ float2 unpack2(u64 v) {
    float2 f; asm("mov.b64 {%0, %1}, %2;" : "=f"(f.x), "=f"(f.y) : "l"(v)); return f;
}
__device__ __forceinline__ u64 fma2(u64 a, u64 b, u64 c) {
    u64 d;
    asm("fma.rn.f32x2 %0, %1, %2, %3;" : "=l"(d) : "l"(a), "l"(b), "l"(c));
    return d;
}
__device__ __forceinline__ float tanh_fast(float a) {
    // tanh(a) = 1 - 2/(e+1), e = 2^(2a*log2e). |a| <= ~8 here -> no clamp.
    float e, r;
    asm("ex2.approx.f32 %0, %1;" : "=f"(e) : "f"(a * 2.8853900817779268f));
    asm("rcp.approx.f32 %0, %1;" : "=f"(r) : "f"(e + 1.0f));
    return fmaf(-2.0f, r, 1.0f);
}

__global__ __launch_bounds__(64)
void rnn_fused_kernel(const float* __restrict__ x,
                      const float* __restrict__ Wih,
                      const float* __restrict__ Whh,
                      const float* __restrict__ bih,
                      const float* __restrict__ bhh,
                      const float* __restrict__ fcw,
                      const float* __restrict__ fcb,
                      float* __restrict__ out) {
    __shared__ float hbuf[2][RPC][HH];   // stride-20-word rows

    const unsigned lane = threadIdx.x & 31u;
    const int wid  = (int)(threadIdx.x >> 5);
    const int part = (int)(lane & 3u);          // output slice (0..3)
    const int kh   = (int)((lane >> 2) & 1u);   // k-half (0/1)
    const int grp  = (int)(lane >> 3);          // row within warp (0..3)
    const int ig   = (int)(lane & 7u);          // lane index within row group
    const unsigned gbase = lane & ~7u;          // base lane of 8-lane group
    const unsigned FULL = 0xFFFFFFFFu;

    const int crow = wid * RPW + grp;           // row slot in CTA (0..7)
    const int row  = blockIdx.x * RPC + crow;   // global batch row

    // ---- per-thread constants ----
    // My k-pairs: p = 2*qq + kh (qq = 0..4), covering k = 2p, 2p+1.
    u64 W2[JPT][5];
    u64 w01[JPT], bias2[JPT];
#pragma unroll
    for (int jj = 0; jj < JPT; ++jj) {
        const int j = part * JPT + jj;
        bias2[jj] = pack2(bih[j] + bhh[j], 0.0f);   // used by kh0 only
        w01[jj]   = pack2(Wih[2 * j], Wih[2 * j + 1]);  // used by kh1 only
#pragma unroll
        for (int qq = 0; qq < 5; ++qq) {
            const int p = 2 * qq + kh;
            W2[jj][qq] = pack2(Whh[j * HH + 2 * p], Whh[j * HH + 2 * p + 1]);
        }
    }

    // h0 = 0 in buffer 0 (kh0 lanes write their part's 5 words)
    if (kh == 0) {
#pragma unroll
        for (int jj = 0; jj < JPT; ++jj)
            hbuf[0][crow][part * JPT + jj] = 0.0f;
    }
    __syncwarp();

    // x: [B, T, 2] as one u64 per (row, t). Lane ig holds steps 8c+ig.
    const u64* xr = reinterpret_cast<const u64*>(x) + (size_t)row * TT;
    u64 xb = xr[ig];
    const int NC = TT / 8;   // 256 chunks of 8 steps

    float h[JPT];

    for (int c = 0; c < NC; ++c) {
        // branch-free prefetch (last iter re-reads chunk 0: in-bounds, unused)
        const int cn = (c + 1 < NC) ? (c + 1) : 0;
        const u64 xn = xr[cn * 8 + ig];

        // hoist all 8 x-broadcasts out of the recurrence chain
        u64 xps[8];
#pragma unroll
        for (int s = 0; s < 8; ++s)
            xps[s] = __shfl_sync(FULL, xb, gbase + s);

#pragma unroll
        for (int s = 0; s < 8; ++s) {
            const int rb = s & 1;   // read buffer (t = 8c+s, parity = s&1)

            // previous-step h pairs of my k-half: 5x LDS.64 at 16B stride
            u64 hpair[5];
            const float* hrow = hbuf[rb][crow];
#pragma unroll
            for (int qq = 0; qq < 5; ++qq)
                hpair[qq] = *reinterpret_cast<const u64*>(hrow + 2 * (2 * qq + kh));

#pragma unroll
            for (int jj = 0; jj < JPT; ++jj) {
                // kh0 seeds with bias, kh1 seeds with the x contribution
                u64 acc = (kh == 0) ? bias2[jj] : fma2(xps[s], w01[jj], 0ull);
#pragma unroll
                for (int qq = 0; qq < 5; ++qq)
                    acc = fma2(hpair[qq], W2[jj][qq], acc);
                const float2 f = unpack2(acc);
                float ps = f.x + f.y;
                ps += __shfl_xor_sync(FULL, ps, 4);   // combine k-halves
                h[jj] = tanh_fast(ps);
            }

            if (kh == 0) {
#pragma unroll
                for (int jj = 0; jj < JPT; ++jj)
                    hbuf[rb ^ 1][crow][part * JPT + jj] = h[jj];
            }
            __syncwarp();
        }
        xb = xn;
    }

    // ---- epilogue: fc head + h_state ----
    float p = 0.0f;
#pragma unroll
    for (int jj = 0; jj < JPT; ++jj)
        p = fmaf(h[jj], fcw[part * JPT + jj], p);
    p += __shfl_xor_sync(FULL, p, 1);
    p += __shfl_xor_sync(FULL, p, 2);
    if (ig == 0) out[row] = p + fcb[0];

    if (kh == 0) {
        float* hs = out + BB;  // h_state [1, B, H] after out [B, 1]
#pragma unroll
        for (int jj = 0; jj < JPT; ++jj)
            hs[(size_t)row * HH + part * JPT + jj] = h[jj];
    }
}

extern "C" void kernel_launch(void* const* d_in, const int* in_sizes, int n_in,
                              void* d_out, int out_size) {
    const float* x   = (const float*)d_in[0];
    const float* Wih = (const float*)d_in[1];
    const float* Whh = (const float*)d_in[2];
    const float* bih = (const float*)d_in[3];
    const float* bhh = (const float*)d_in[4];
    const float* fcw = (const float*)d_in[5];
    const float* fcb = (const float*)d_in[6];
    float* out = (float*)d_out;

    const int nblocks = BB / RPC;              // 1024 CTAs of 64 threads
    rnn_fused_kernel<<<nblocks, 64>>>(x, Wih, Whh, bih, bhh, fcw, fcb, out);
}

// round 10
// speedup vs baseline: 1.4264x; 1.4264x over previous
#include <cuda_runtime.h>
#include <cuda_bf16.h>

// RNN: B=8192, T=2048, I=2, H=20
//   h_{t+1} = tanh(x_t @ W_ih^T + b_ih + b_hh + h_t @ W_hh^T)
//   out = h_T @ fc_w^T + fc_b ; h_state = h_T
//
// R8: 10 lanes per row, 2 hidden units per lane (units 2ig, 2ig+1), 3 rows
// per warp (lanes 30,31 idle). 2731 warps = 4.6/SMSP (2.7x R3 coverage).
// Each lane's unit pair is a natural f32x2 pair: tanh outputs pack to one
// STS.64; the full h vector returns as 5 broadcast LDS.128 (conflict-free).
// No reduction shuffles (each output owned end-to-end by one lane).
// Per-lane step: 5 LDS.128 + 22 fma2 + 2 FADD + 2 tanh + 1 STS.64 + sync.

#define BB 8192
#define TT 2048
#define HH 20
#define RPWARP 3      // rows per warp

typedef unsigned long long u64;

__device__ __forceinline__ u64 pack2(float lo, float hi) {
    u64 r; asm("mov.b64 %0, {%1, %2};" : "=l"(r) : "f"(lo), "f"(hi)); return r;
}
__device__ __forceinline__ float2 unpack2(u64 v) {
    float2 f; asm("mov.b64 {%0, %1}, %2;" : "=f"(f.x), "=f"(f.y) : "l"(v)); return f;
}
__device__ __forceinline__ u64 fma2(u64 a, u64 b, u64 c) {
    u64 d;
    asm("fma.rn.f32x2 %0, %1, %2, %3;" : "=l"(d) : "l"(a), "l"(b), "l"(c));
    return d;
}
__device__ __forceinline__ float tanh_fast(float a) {
    // tanh(a) = 1 - 2/(e+1), e = 2^(2a*log2e). |a| <= ~8 here -> no clamp.
    float e, r;
    asm("ex2.approx.f32 %0, %1;" : "=f"(e) : "f"(a * 2.8853900817779268f));
    asm("rcp.approx.f32 %0, %1;" : "=f"(r) : "f"(e + 1.0f));
    return fmaf(-2.0f, r, 1.0f);
}

__global__ __launch_bounds__(32)
void rnn_fused_kernel(const float* __restrict__ x,
                      const float* __restrict__ Wih,
                      const float* __restrict__ Whh,
                      const float* __restrict__ bih,
                      const float* __restrict__ bhh,
                      const float* __restrict__ fcw,
                      const float* __restrict__ fcb,
                      float* __restrict__ out) {
    __shared__ float hbuf[2][RPWARP][HH];   // stride-20-word rows

    const int lane = (int)(threadIdx.x & 31u);
    const int grp  = (lane < 30) ? (lane / 10) : 2;   // row group 0..2
    const int ig   = lane - grp * 10;                 // 0..9 active, 10..11 idle
    const bool act = (ig < 10);
    const unsigned FULL = 0xFFFFFFFFu;

    const int row  = blockIdx.x * RPWARP + grp;       // global batch row
    const bool vrow = (row < BB);
    const int row_c = vrow ? row : (BB - 1);          // clamped for loads

    // ---- per-thread constants: units u0=2*ig, u1=2*ig+1 ----
    const int igc = act ? ig : 9;
    const int u0 = 2 * igc, u1 = u0 + 1;
    u64 W2[2][HH / 2];   // k-pairs for my two units
    u64 w01[2], bias2[2];
#pragma unroll
    for (int uu = 0; uu < 2; ++uu) {
        const int j = u0 + uu;
        bias2[uu] = pack2(bih[j] + bhh[j], 0.0f);
        w01[uu]   = pack2(Wih[2 * j], Wih[2 * j + 1]);
#pragma unroll
        for (int q = 0; q < HH / 2; ++q)
            W2[uu][q] = pack2(Whh[j * HH + 2 * q], Whh[j * HH + 2 * q + 1]);
    }

    // h0 = 0 in buffer 0
    if (act) {
        hbuf[0][grp][u0] = 0.0f;
        hbuf[0][grp][u1] = 0.0f;
    }
    __syncwarp();

    // x: [B, T, 2] as one u64 per (row, t). Lanes ig<8 hold steps 8c+ig.
    const u64* xr = reinterpret_cast<const u64*>(x) + (size_t)row_c * TT;
    u64 xb = (ig < 8) ? xr[ig] : 0ull;
    const int NC = TT / 8;   // 256 chunks of 8 steps

    float h0 = 0.0f, h1 = 0.0f;

    for (int c = 0; c < NC; ++c) {
        // branch-free prefetch (last iter re-reads chunk 0: in-bounds, unused)
        const int cn = (c + 1 < NC) ? (c + 1) : 0;
        const u64 xn = (ig < 8) ? xr[cn * 8 + ig] : 0ull;

#pragma unroll
        for (int s = 0; s < 8; ++s) {
            const int rb = s & 1;   // t = 8c+s; parity = s&1
            const u64 xp = __shfl_sync(FULL, xb, grp * 10 + s);

            // full previous h vector as pairs: 5 broadcast LDS.128
            u64 hp[HH / 2];
            const ulonglong2* hq =
                reinterpret_cast<const ulonglong2*>(hbuf[rb][grp]);
#pragma unroll
            for (int q = 0; q < 5; ++q) {
                const ulonglong2 v = hq[q];
                hp[2 * q]     = v.x;
                hp[2 * q + 1] = v.y;
            }

            // two outputs, each a full k=20 contraction (independent chains)
            u64 a0 = fma2(xp, w01[0], bias2[0]);
            u64 a1 = fma2(xp, w01[1], bias2[1]);
#pragma unroll
            for (int q = 0; q < HH / 2; ++q) {
                a0 = fma2(hp[q], W2[0][q], a0);
                a1 = fma2(hp[q], W2[1][q], a1);
            }
            const float2 f0 = unpack2(a0);
            const float2 f1 = unpack2(a1);
            h0 = tanh_fast(f0.x + f0.y);
            h1 = tanh_fast(f1.x + f1.y);

            if (act)
                *reinterpret_cast<u64*>(&hbuf[rb ^ 1][grp][u0]) = pack2(h0, h1);
            __syncwarp();
        }
        xb = xn;
    }

    // ---- epilogue ----
    // h_state [1, B, H] lives right after out [B, 1]
    if (act && vrow) {
        float* hs = out + BB;
        hs[(size_t)row * HH + u0] = h0;
        hs[(size_t)row * HH + u1] = h1;
    }
    // final h is in buffer 0 (step 2047 wrote rb^1 = 0)
    if (ig == 0 && vrow) {
        float p = fcb[0];
#pragma unroll
        for (int k = 0; k < HH; ++k)
            p = fmaf(hbuf[0][grp][k], fcw[k], p);
        out[row] = p;
    }
}

extern "C" void kernel_launch(void* const* d_in, const int* in_sizes, int n_in,
                              void* d_out, int out_size) {
    const float* x   = (const float*)d_in[0];
    const float* Wih = (const float*)d_in[1];
    const float* Whh = (const float*)d_in[2];
    const float* bih = (const float*)d_in[3];
    const float* bhh = (const float*)d_in[4];
    const float* fcw = (const float*)d_in[5];
    const float* fcb = (const float*)d_in[6];
    float* out = (float*)d_out;

    const int nblocks = (BB + RPWARP - 1) / RPWARP;   // 2731 single-warp CTAs
    rnn_fused_kernel<<<nblocks, 32>>>(x, Wih, Whh, bih, bhh, fcw, fcb, out);
}